// round 1
// baseline (speedup 1.0000x reference)
#include <cuda_runtime.h>
#include <cstdint>

#define N_PTS 8192
#define E_DIM 256
#define NUM_CLASSES 100
#define MARGIN 0.1f
#define EPS_F 1e-4f

#define BM 64
#define BN 64
#define RS 260            // padded shared row stride in floats (260*4B; odd/4 -> limits bank conflicts)
#define NTILES (N_PTS / BN)
#define NBLOCKS (N_PTS / BM)

// Persistent scratch (no allocations allowed)
__device__ float g_sq[N_PTS];
__device__ int   g_hist[NUM_CLASSES];
__device__ float g_partial[NBLOCKS];

// ---------------------------------------------------------------------------
// Zero the histogram (g_partial is fully overwritten each launch; no zero needed)
// ---------------------------------------------------------------------------
__global__ void zero_kernel() {
    int t = threadIdx.x;
    if (t < NUM_CLASSES) g_hist[t] = 0;
}

// ---------------------------------------------------------------------------
// Per-row squared norms + label histogram. One warp per row.
// ---------------------------------------------------------------------------
__global__ void prep_kernel(const float* __restrict__ X, const int* __restrict__ lab) {
    int warp = (blockIdx.x * blockDim.x + threadIdx.x) >> 5;
    int lane = threadIdx.x & 31;
    if (warp >= N_PTS) return;
    const float4* row = (const float4*)(X + (size_t)warp * E_DIM);
    float s = 0.f;
#pragma unroll
    for (int i = 0; i < 2; ++i) {
        float4 v = row[lane + 32 * i];
        s += v.x * v.x + v.y * v.y + v.z * v.z + v.w * v.w;
    }
#pragma unroll
    for (int o = 16; o; o >>= 1) s += __shfl_xor_sync(0xffffffffu, s, o);
    if (lane == 0) {
        g_sq[warp] = s;
        atomicAdd(&g_hist[lab[warp]], 1);
    }
}

// ---------------------------------------------------------------------------
// Fused GEMM + triplet-ratio epilogue.
// Block = BM rows. Loops over all column tiles of BN. 256 threads, 4x4 micro
// tile per thread (j strided by 16 for conflict-friendly b-frag loads).
// num/den accumulate in registers across the whole column sweep.
// ---------------------------------------------------------------------------
__global__ void __launch_bounds__(256, 1)
triplet_main_kernel(const float* __restrict__ X, const int* __restrict__ lab) {
    extern __shared__ float sm[];
    float* As = sm;                 // BM x RS
    float* Bs = sm + BM * RS;       // BN x RS

    __shared__ float sqb[BN];
    __shared__ int   lbb[BN];
    __shared__ float red[BM * 16];  // cross-tx reduction buffer
    __shared__ float wsum[2];

    const int tid = threadIdx.x;
    const int tx  = tid & 15;
    const int ty  = tid >> 4;
    const int row0 = blockIdx.x * BM;

    // Load A tile (BM x E) into padded shared, row-major.
    for (int idx = tid; idx < BM * (E_DIM / 4); idx += 256) {
        int r  = idx >> 6;
        int c4 = idx & 63;
        float4 v = ((const float4*)(X + (size_t)(row0 + r) * E_DIM))[c4];
        *(float4*)&As[r * RS + c4 * 4] = v;
    }

    float sqa[4];
    int   la[4];
#pragma unroll
    for (int i = 0; i < 4; ++i) {
        int r = row0 + ty * 4 + i;
        sqa[i] = g_sq[r];
        la[i]  = lab[r];
    }

    float num[4] = {0.f, 0.f, 0.f, 0.f};
    float den[4] = {0.f, 0.f, 0.f, 0.f};

    for (int jt = 0; jt < NTILES; ++jt) {
        const int col0 = jt * BN;
        __syncthreads();   // protect previous tile's Bs/sqb/lbb before overwrite
        for (int idx = tid; idx < BN * (E_DIM / 4); idx += 256) {
            int r  = idx >> 6;
            int c4 = idx & 63;
            float4 v = ((const float4*)(X + (size_t)(col0 + r) * E_DIM))[c4];
            *(float4*)&Bs[r * RS + c4 * 4] = v;
        }
        if (tid < BN) {
            sqb[tid] = g_sq[col0 + tid];
            lbb[tid] = lab[col0 + tid];
        }
        __syncthreads();

        float acc[4][4];
#pragma unroll
        for (int i = 0; i < 4; ++i)
#pragma unroll
            for (int j = 0; j < 4; ++j) acc[i][j] = 0.f;

#pragma unroll 4
        for (int kq = 0; kq < E_DIM / 4; ++kq) {
            float4 a4[4], b4[4];
#pragma unroll
            for (int i = 0; i < 4; ++i)
                a4[i] = *(const float4*)&As[(ty * 4 + i) * RS + kq * 4];
#pragma unroll
            for (int j = 0; j < 4; ++j)
                b4[j] = *(const float4*)&Bs[(tx + 16 * j) * RS + kq * 4];
#pragma unroll
            for (int i = 0; i < 4; ++i)
#pragma unroll
                for (int j = 0; j < 4; ++j) {
                    acc[i][j] = fmaf(a4[i].x, b4[j].x, acc[i][j]);
                    acc[i][j] = fmaf(a4[i].y, b4[j].y, acc[i][j]);
                    acc[i][j] = fmaf(a4[i].z, b4[j].z, acc[i][j]);
                    acc[i][j] = fmaf(a4[i].w, b4[j].w, acc[i][j]);
                }
        }

        // Epilogue: distances + pos/neg accumulation (registers persist).
#pragma unroll
        for (int j = 0; j < 4; ++j) {
            int jj  = tx + 16 * j;
            float sj = sqb[jj];
            int   lj = lbb[jj];
#pragma unroll
            for (int i = 0; i < 4; ++i) {
                float v = fmaxf(sqa[i] + sj - 2.f * acc[i][j], EPS_F);
                float d;
                asm("sqrt.approx.f32 %0, %1;" : "=f"(d) : "f"(v));
                if (la[i] == lj) {
                    num[i] += d;
                } else {
                    float r;
                    asm("rcp.approx.f32 %0, %1;" : "=f"(r) : "f"(d + MARGIN));
                    den[i] += r;
                }
            }
        }
    }

    // Reduce num across the 16 tx threads sharing each row.
    __syncthreads();
#pragma unroll
    for (int i = 0; i < 4; ++i) red[(ty * 4 + i) * 16 + tx] = num[i];
    __syncthreads();
    float rn = 0.f;
    if (tid < BM) {
#pragma unroll
        for (int t = 0; t < 16; ++t) rn += red[tid * 16 + t];
    }
    __syncthreads();
#pragma unroll
    for (int i = 0; i < 4; ++i) red[(ty * 4 + i) * 16 + tx] = den[i];
    __syncthreads();

    if (tid < BM) {
        float rd = 0.f;
#pragma unroll
        for (int t = 0; t < 16; ++t) rd += red[tid * 16 + t];
        float p = rn * rd;
#pragma unroll
        for (int o = 16; o; o >>= 1) p += __shfl_xor_sync(0xffffffffu, p, o);
        if ((tid & 31) == 0) wsum[tid >> 5] = p;
    }
    __syncthreads();
    if (tid == 0) g_partial[blockIdx.x] = wsum[0] + wsum[1];
}

// ---------------------------------------------------------------------------
// Final reduction: loss = sum(partials) / sum_c h^2 (N - h)
// ---------------------------------------------------------------------------
__global__ void finalize_kernel(float* __restrict__ out) {
    __shared__ double s1[128];
    __shared__ double s2[128];
    int t = threadIdx.x;
    double a = (t < NBLOCKS) ? (double)g_partial[t] : 0.0;
    double b = 0.0;
    if (t < NUM_CLASSES) {
        double h = (double)g_hist[t];
        b = h * h * ((double)N_PTS - h);
    }
    s1[t] = a;
    s2[t] = b;
    __syncthreads();
    for (int o = 64; o; o >>= 1) {
        if (t < o) { s1[t] += s1[t + o]; s2[t] += s2[t + o]; }
        __syncthreads();
    }
    if (t == 0) out[0] = (float)(s1[0] / s2[0]);
}

// ---------------------------------------------------------------------------
extern "C" void kernel_launch(void* const* d_in, const int* in_sizes, int n_in,
                              void* d_out, int out_size) {
    const float* X   = (const float*)d_in[0];
    const int*   lab = (const int*)d_in[1];
    float*       out = (float*)d_out;

    zero_kernel<<<1, 128>>>();
    prep_kernel<<<N_PTS / 8, 256>>>(X, lab);

    size_t smem = (size_t)2 * BM * RS * sizeof(float);  // 133,120 B
    cudaFuncSetAttribute(triplet_main_kernel,
                         cudaFuncAttributeMaxDynamicSharedMemorySize, (int)smem);
    triplet_main_kernel<<<NBLOCKS, 256, smem>>>(X, lab);

    finalize_kernel<<<1, 128>>>(out);
}

// round 7
// speedup vs baseline: 3.8943x; 3.8943x over previous
#include <cuda_runtime.h>
#include <cstdint>

#define N_PTS 8192
#define E_DIM 256
#define NUM_CLASSES 100
#define MARGIN 0.1f
#define EPS_F 1e-4f

#define BM 128
#define BN 64
#define SA 260              // padded row stride (floats); 260 % 32 == 4 -> conflict-free frags
#define SB 260
#define NROWTILES (N_PTS / BM)    // 64
#define NBLOCKS (NROWTILES * 2)   // 128 (2 column halves)
#define HALF_TILES ((N_PTS / 2) / BN)  // 64 col tiles per half

__device__ float g_sq[N_PTS];
__device__ int   g_hist[NUM_CLASSES];
__device__ float g_num[2 * N_PTS];
__device__ float g_den[2 * N_PTS];

__device__ __forceinline__ float to_tf32(float x) {
    unsigned u;
    asm("cvt.rna.tf32.f32 %0, %1;" : "=r"(u) : "f"(x));
    return __uint_as_float(u);
}

__device__ __forceinline__ void mma_tf32(float acc[4], const float a[4], const float b[2]) {
    const unsigned* A = reinterpret_cast<const unsigned*>(a);
    const unsigned* B = reinterpret_cast<const unsigned*>(b);
    asm volatile(
        "mma.sync.aligned.m16n8k8.row.col.f32.tf32.tf32.f32 "
        "{%0,%1,%2,%3}, {%4,%5,%6,%7}, {%8,%9}, {%0,%1,%2,%3};"
        : "+f"(acc[0]), "+f"(acc[1]), "+f"(acc[2]), "+f"(acc[3])
        : "r"(A[0]), "r"(A[1]), "r"(A[2]), "r"(A[3]), "r"(B[0]), "r"(B[1]));
}

// ---------------------------------------------------------------------------
__global__ void zero_kernel() {
    int t = threadIdx.x;
    if (t < NUM_CLASSES) g_hist[t] = 0;
}

// Per-row squared norms + label histogram. One warp per row.
__global__ void prep_kernel(const float* __restrict__ X, const int* __restrict__ lab) {
    int warp = (blockIdx.x * blockDim.x + threadIdx.x) >> 5;
    int lane = threadIdx.x & 31;
    if (warp >= N_PTS) return;
    const float4* row = (const float4*)(X + (size_t)warp * E_DIM);
    float s = 0.f;
#pragma unroll
    for (int i = 0; i < 2; ++i) {
        float4 v = row[lane + 32 * i];
        s += v.x * v.x + v.y * v.y + v.z * v.z + v.w * v.w;
    }
#pragma unroll
    for (int o = 16; o; o >>= 1) s += __shfl_xor_sync(0xffffffffu, s, o);
    if (lane == 0) {
        g_sq[warp] = s;
        atomicAdd(&g_hist[lab[warp]], 1);
    }
}

// ---------------------------------------------------------------------------
// tf32 tensor-core Gram + fused triplet-ratio epilogue.
// Block = 128 rows x one column half (4096 cols in 64 tiles of 64).
// 8 warps: warp grid 4(m) x 2(n); warp tile 32x32; mma m16n8k8 tf32.
// B tile = 64 x 256 floats = 4096 float4 = 16 float4 PER THREAD.
// ---------------------------------------------------------------------------
__global__ void __launch_bounds__(256, 1)
triplet_main_kernel(const float* __restrict__ X, const int* __restrict__ lab) {
    extern __shared__ float sm[];
    float* As = sm;             // BM x SA
    float* Bs = sm + BM * SA;   // BN x SB

    __shared__ float sqb_s[BN];
    __shared__ int   lbb_s[BN];
    __shared__ float red_n[BM][2];
    __shared__ float red_d[BM][2];

    const int tid  = threadIdx.x;
    const int w    = tid >> 5, lane = tid & 31;
    const int wm   = w >> 1,   wn   = w & 1;
    const int g    = lane >> 2, cc  = lane & 3;
    const int rt   = blockIdx.x >> 1;
    const int h    = blockIdx.x & 1;
    const int row0 = rt * BM;
    const int cbase = h * (N_PTS / 2);
    const float DIAG_D = sqrtf(EPS_F);

    // Load + tf32-convert A tile (resident for whole sweep): 32 float4/thread.
    for (int idx = tid; idx < BM * (E_DIM / 4); idx += 256) {
        int r = idx >> 6, c4 = idx & 63;
        float4 v = ((const float4*)(X + (size_t)(row0 + r) * E_DIM))[c4];
        v.x = to_tf32(v.x); v.y = to_tf32(v.y);
        v.z = to_tf32(v.z); v.w = to_tf32(v.w);
        *(float4*)&As[r * SA + c4 * 4] = v;
    }

    // Per-thread row metadata: rows wm*32 + mf*16 + g + 8*hi, id = mf*2+hi
    float sqa[4]; int la[4];
#pragma unroll
    for (int mf = 0; mf < 2; ++mf)
#pragma unroll
        for (int hi = 0; hi < 2; ++hi) {
            int r = row0 + wm * 32 + mf * 16 + g + hi * 8;
            sqa[mf * 2 + hi] = g_sq[r];
            la[mf * 2 + hi]  = lab[r];
        }

    float num[4] = {0.f, 0.f, 0.f, 0.f};
    float den[4] = {0.f, 0.f, 0.f, 0.f};

    for (int jt = 0; jt < HALF_TILES; ++jt) {
        const int col0 = cbase + jt * BN;
        __syncthreads();  // previous tile's Bs fully consumed

        // B tile: gather 16 float4/thread first (batched LDGs, one latency
        // exposure), then convert+store to shared.
        {
            float4 tmp[16];
#pragma unroll
            for (int q = 0; q < 16; ++q) {
                int idx = tid + q * 256;          // 0..4095
                int r = idx >> 6, c4 = idx & 63;
                tmp[q] = ((const float4*)(X + (size_t)(col0 + r) * E_DIM))[c4];
            }
#pragma unroll
            for (int q = 0; q < 16; ++q) {
                int idx = tid + q * 256;
                int r = idx >> 6, c4 = idx & 63;
                float4 v = tmp[q];
                v.x = to_tf32(v.x); v.y = to_tf32(v.y);
                v.z = to_tf32(v.z); v.w = to_tf32(v.w);
                *(float4*)&Bs[r * SB + c4 * 4] = v;
            }
        }
        if (tid < BN) {
            sqb_s[tid] = g_sq[col0 + tid];
            lbb_s[tid] = lab[col0 + tid];
        }
        __syncthreads();

        float acc[2][4][4];
#pragma unroll
        for (int mf = 0; mf < 2; ++mf)
#pragma unroll
            for (int nf = 0; nf < 4; ++nf)
#pragma unroll
                for (int e = 0; e < 4; ++e) acc[mf][nf][e] = 0.f;

#pragma unroll 4
        for (int ks = 0; ks < E_DIM / 8; ++ks) {
            const int kc = ks * 8;
            float a[2][4], b[4][2];
#pragma unroll
            for (int mf = 0; mf < 2; ++mf) {
                int r = wm * 32 + mf * 16 + g;
                a[mf][0] = As[r * SA + kc + cc];
                a[mf][1] = As[(r + 8) * SA + kc + cc];
                a[mf][2] = As[r * SA + kc + cc + 4];
                a[mf][3] = As[(r + 8) * SA + kc + cc + 4];
            }
#pragma unroll
            for (int nf = 0; nf < 4; ++nf) {
                int n = wn * 32 + nf * 8 + g;
                b[nf][0] = Bs[n * SB + kc + cc];
                b[nf][1] = Bs[n * SB + kc + cc + 4];
            }
#pragma unroll
            for (int mf = 0; mf < 2; ++mf)
#pragma unroll
                for (int nf = 0; nf < 4; ++nf)
                    mma_tf32(acc[mf][nf], a[mf], b[nf]);
        }

        // Epilogue: one MUFU (rsqrt) per element; series for 1/(d+margin).
        float sj[4][2]; int lj[4][2];
#pragma unroll
        for (int nf = 0; nf < 4; ++nf)
#pragma unroll
            for (int e0 = 0; e0 < 2; ++e0) {
                int jl = wn * 32 + nf * 8 + 2 * cc + e0;
                sj[nf][e0] = sqb_s[jl];
                lj[nf][e0] = lbb_s[jl];
            }

#pragma unroll
        for (int mf = 0; mf < 2; ++mf)
#pragma unroll
            for (int nf = 0; nf < 4; ++nf)
#pragma unroll
                for (int e = 0; e < 4; ++e) {
                    int hi = e >> 1, e0 = e & 1;
                    int id = mf * 2 + hi;
                    int iglob = row0 + wm * 32 + mf * 16 + g + hi * 8;
                    int jglob = col0 + wn * 32 + nf * 8 + 2 * cc + e0;
                    float v = fmaxf(sqa[id] + sj[nf][e0] - 2.f * acc[mf][nf][e], EPS_F);
                    float r;
                    asm("rsqrt.approx.f32 %0, %1;" : "=f"(r) : "f"(v));
                    if (la[id] == lj[nf][e0]) {
                        num[id] += (iglob == jglob) ? DIAG_D : v * r;
                    } else {
                        float t  = MARGIN * r;
                        float u  = 1.f - t;
                        float s2 = fmaf(t * t, u, u);   // (1-t)(1+t^2)
                        den[id] += r * s2;
                    }
                }
    }

    // Reduce across the 4 lanes sharing a row (xor 1,2 stays within quad).
#pragma unroll
    for (int id = 0; id < 4; ++id) {
        num[id] += __shfl_xor_sync(0xffffffffu, num[id], 1);
        num[id] += __shfl_xor_sync(0xffffffffu, num[id], 2);
        den[id] += __shfl_xor_sync(0xffffffffu, den[id], 1);
        den[id] += __shfl_xor_sync(0xffffffffu, den[id], 2);
    }
    __syncthreads();  // all tiles consumed; smem reuse safe
    if (cc == 0) {
#pragma unroll
        for (int mf = 0; mf < 2; ++mf)
#pragma unroll
            for (int hi = 0; hi < 2; ++hi) {
                int rl = wm * 32 + mf * 16 + g + hi * 8;
                red_n[rl][wn] = num[mf * 2 + hi];
                red_d[rl][wn] = den[mf * 2 + hi];
            }
    }
    __syncthreads();
    if (tid < BM) {
        g_num[h * N_PTS + row0 + tid] = red_n[tid][0] + red_n[tid][1];
        g_den[h * N_PTS + row0 + tid] = red_d[tid][0] + red_d[tid][1];
    }
}

// ---------------------------------------------------------------------------
// Must be launched with 256 threads (stride-256 row loop + 256-entry reduce).
__global__ void finalize_kernel(float* __restrict__ out) {
    __shared__ double s1[256];
    __shared__ double s2[256];
    int t = threadIdx.x;
    double a = 0.0;
    for (int row = t; row < N_PTS; row += 256) {
        double n = (double)g_num[row] + (double)g_num[N_PTS + row];
        double d = (double)g_den[row] + (double)g_den[N_PTS + row];
        a += n * d;
    }
    double b = 0.0;
    if (t < NUM_CLASSES) {
        double hh = (double)g_hist[t];
        b = hh * hh * ((double)N_PTS - hh);
    }
    s1[t] = a; s2[t] = b;
    __syncthreads();
    for (int o = 128; o; o >>= 1) {
        if (t < o) { s1[t] += s1[t + o]; s2[t] += s2[t + o]; }
        __syncthreads();
    }
    if (t == 0) out[0] = (float)(s1[0] / s2[0]);
}

// ---------------------------------------------------------------------------
extern "C" void kernel_launch(void* const* d_in, const int* in_sizes, int n_in,
                              void* d_out, int out_size) {
    const float* X   = (const float*)d_in[0];
    const int*   lab = (const int*)d_in[1];
    float*       out = (float*)d_out;

    zero_kernel<<<1, 128>>>();
    prep_kernel<<<N_PTS / 8, 256>>>(X, lab);

    size_t smem = (size_t)(BM + BN) * SA * sizeof(float);  // 199,680 B
    cudaFuncSetAttribute(triplet_main_kernel,
                         cudaFuncAttributeMaxDynamicSharedMemorySize, (int)smem);
    triplet_main_kernel<<<NBLOCKS, 256, smem>>>(X, lab);

    finalize_kernel<<<1, 256>>>(out);
}

// round 10
// speedup vs baseline: 3.9695x; 1.0193x over previous
#include <cuda_runtime.h>
#include <cuda_bf16.h>
#include <cstdint>

#define N_PTS 8192
#define E_DIM 256
#define NUM_CLASSES 100
#define MARGIN 0.1f
#define EPS_F 1e-4f

#define BM 128
#define BN 64
#define SAB 264             // padded row stride in bf16 elems (528B; 132 words == 4 mod 32)
#define NROWTILES (N_PTS / BM)    // 64
#define NBLOCKS (NROWTILES * 2)   // 128 (2 column halves)
#define HALF_TILES ((N_PTS / 2) / BN)  // 64 col tiles per half

__device__ float g_sq[N_PTS];
__device__ int   g_hist[NUM_CLASSES];
__device__ float g_num[2 * N_PTS];
__device__ float g_den[2 * N_PTS];
__device__ __nv_bfloat16 g_xb[(size_t)N_PTS * E_DIM];   // bf16 copy of X (4MB)

__device__ __forceinline__ void mma_bf16(float acc[4], const uint32_t a[4],
                                         const uint32_t b[2]) {
    asm volatile(
        "mma.sync.aligned.m16n8k16.row.col.f32.bf16.bf16.f32 "
        "{%0,%1,%2,%3}, {%4,%5,%6,%7}, {%8,%9}, {%0,%1,%2,%3};"
        : "+f"(acc[0]), "+f"(acc[1]), "+f"(acc[2]), "+f"(acc[3])
        : "r"(a[0]), "r"(a[1]), "r"(a[2]), "r"(a[3]), "r"(b[0]), "r"(b[1]));
}

// ---------------------------------------------------------------------------
__global__ void zero_kernel() {
    int t = threadIdx.x;
    if (t < NUM_CLASSES) g_hist[t] = 0;
}

// Per-row squared norms + label histogram + bf16 conversion. One warp per row;
// lane L owns cols 8L..8L+7 (one uint4 of bf16).
__global__ void prep_kernel(const float* __restrict__ X, const int* __restrict__ lab) {
    int warp = (blockIdx.x * blockDim.x + threadIdx.x) >> 5;
    int lane = threadIdx.x & 31;
    if (warp >= N_PTS) return;
    const float4* row = (const float4*)(X + (size_t)warp * E_DIM);
    float4 v0 = row[2 * lane];
    float4 v1 = row[2 * lane + 1];
    float s = v0.x * v0.x + v0.y * v0.y + v0.z * v0.z + v0.w * v0.w
            + v1.x * v1.x + v1.y * v1.y + v1.z * v1.z + v1.w * v1.w;

    __nv_bfloat162 p0 = __floats2bfloat162_rn(v0.x, v0.y);
    __nv_bfloat162 p1 = __floats2bfloat162_rn(v0.z, v0.w);
    __nv_bfloat162 p2 = __floats2bfloat162_rn(v1.x, v1.y);
    __nv_bfloat162 p3 = __floats2bfloat162_rn(v1.z, v1.w);
    uint4 u;
    u.x = *(uint32_t*)&p0; u.y = *(uint32_t*)&p1;
    u.z = *(uint32_t*)&p2; u.w = *(uint32_t*)&p3;
    ((uint4*)(g_xb + (size_t)warp * E_DIM))[lane] = u;

#pragma unroll
    for (int o = 16; o; o >>= 1) s += __shfl_xor_sync(0xffffffffu, s, o);
    if (lane == 0) {
        g_sq[warp] = s;
        atomicAdd(&g_hist[lab[warp]], 1);
    }
}

// ---------------------------------------------------------------------------
// bf16 m16n8k16 tensor-core Gram + fused triplet-ratio epilogue.
// Block = 128 rows x one column half (4096 cols in 64 tiles of 64).
// 8 warps: warp grid 4(m) x 2(n); warp tile 32x32.
// ---------------------------------------------------------------------------
__global__ void __launch_bounds__(256, 1)
triplet_main_kernel(const int* __restrict__ lab) {
    extern __shared__ __nv_bfloat16 smb[];
    __nv_bfloat16* As = smb;                 // BM x SAB
    __nv_bfloat16* Bs = smb + BM * SAB;      // BN x SAB

    __shared__ float sqb_s[BN];
    __shared__ int   lbb_s[BN];
    __shared__ float red_n[BM][2];
    __shared__ float red_d[BM][2];

    const int tid  = threadIdx.x;
    const int w    = tid >> 5, lane = tid & 31;
    const int wm   = w >> 1,   wn   = w & 1;
    const int g    = lane >> 2, cc  = lane & 3;
    const int rt   = blockIdx.x >> 1;
    const int h    = blockIdx.x & 1;
    const int row0 = rt * BM;
    const int cbase = h * (N_PTS / 2);
    const float DIAG_D = sqrtf(EPS_F);

    // A tile (bf16, resident): 128 rows x 32 uint4/row = 4096 uint4, 16/thread.
    for (int q = 0; q < 16; ++q) {
        int idx = tid + q * 256;
        int r = idx >> 5, c8 = idx & 31;
        uint4 u = ((const uint4*)(g_xb + (size_t)(row0 + r) * E_DIM))[c8];
        *(uint4*)(As + (size_t)r * SAB + c8 * 8) = u;
    }

    float sqa[4]; int la[4];
#pragma unroll
    for (int mf = 0; mf < 2; ++mf)
#pragma unroll
        for (int hi = 0; hi < 2; ++hi) {
            int r = row0 + wm * 32 + mf * 16 + g + hi * 8;
            sqa[mf * 2 + hi] = g_sq[r];
            la[mf * 2 + hi]  = lab[r];
        }

    float num[4] = {0.f, 0.f, 0.f, 0.f};
    float den[4] = {0.f, 0.f, 0.f, 0.f};

    for (int jt = 0; jt < HALF_TILES; ++jt) {
        const int col0 = cbase + jt * BN;
        __syncthreads();  // previous tile's Bs fully consumed

        // B tile: 64 rows x 32 uint4/row = 2048 uint4, 8/thread (batched LDGs).
        {
            uint4 tmp[8];
#pragma unroll
            for (int q = 0; q < 8; ++q) {
                int idx = tid + q * 256;
                int r = idx >> 5, c8 = idx & 31;
                tmp[q] = ((const uint4*)(g_xb + (size_t)(col0 + r) * E_DIM))[c8];
            }
#pragma unroll
            for (int q = 0; q < 8; ++q) {
                int idx = tid + q * 256;
                int r = idx >> 5, c8 = idx & 31;
                *(uint4*)(Bs + (size_t)r * SAB + c8 * 8) = tmp[q];
            }
        }
        if (tid < BN) {
            sqb_s[tid] = g_sq[col0 + tid];
            lbb_s[tid] = lab[col0 + tid];
        }
        __syncthreads();

        float acc[2][4][4];
#pragma unroll
        for (int mf = 0; mf < 2; ++mf)
#pragma unroll
            for (int nf = 0; nf < 4; ++nf)
#pragma unroll
                for (int e = 0; e < 4; ++e) acc[mf][nf][e] = 0.f;

#pragma unroll 4
        for (int ks = 0; ks < E_DIM / 16; ++ks) {
            const int kc = ks * 16;
            uint32_t a[2][4], b[4][2];
#pragma unroll
            for (int mf = 0; mf < 2; ++mf) {
                int r = wm * 32 + mf * 16 + g;
                a[mf][0] = *(const uint32_t*)(As + (size_t)r * SAB + kc + 2 * cc);
                a[mf][1] = *(const uint32_t*)(As + (size_t)(r + 8) * SAB + kc + 2 * cc);
                a[mf][2] = *(const uint32_t*)(As + (size_t)r * SAB + kc + 2 * cc + 8);
                a[mf][3] = *(const uint32_t*)(As + (size_t)(r + 8) * SAB + kc + 2 * cc + 8);
            }
#pragma unroll
            for (int nf = 0; nf < 4; ++nf) {
                int n = wn * 32 + nf * 8 + g;
                b[nf][0] = *(const uint32_t*)(Bs + (size_t)n * SAB + kc + 2 * cc);
                b[nf][1] = *(const uint32_t*)(Bs + (size_t)n * SAB + kc + 2 * cc + 8);
            }
#pragma unroll
            for (int mf = 0; mf < 2; ++mf)
#pragma unroll
                for (int nf = 0; nf < 4; ++nf)
                    mma_bf16(acc[mf][nf], a[mf], b[nf]);
        }

        // Epilogue: one MUFU (rsqrt) per element; series for 1/(d+margin).
        float sj[4][2]; int lj[4][2];
#pragma unroll
        for (int nf = 0; nf < 4; ++nf)
#pragma unroll
            for (int e0 = 0; e0 < 2; ++e0) {
                int jl = wn * 32 + nf * 8 + 2 * cc + e0;
                sj[nf][e0] = sqb_s[jl];
                lj[nf][e0] = lbb_s[jl];
            }

#pragma unroll
        for (int mf = 0; mf < 2; ++mf)
#pragma unroll
            for (int nf = 0; nf < 4; ++nf)
#pragma unroll
                for (int e = 0; e < 4; ++e) {
                    int hi = e >> 1, e0 = e & 1;
                    int id = mf * 2 + hi;
                    int iglob = row0 + wm * 32 + mf * 16 + g + hi * 8;
                    int jglob = col0 + wn * 32 + nf * 8 + 2 * cc + e0;
                    float v = fmaxf(sqa[id] + sj[nf][e0] - 2.f * acc[mf][nf][e], EPS_F);
                    float r;
                    asm("rsqrt.approx.f32 %0, %1;" : "=f"(r) : "f"(v));
                    if (la[id] == lj[nf][e0]) {
                        num[id] += (iglob == jglob) ? DIAG_D : v * r;
                    } else {
                        float t  = MARGIN * r;
                        float u  = 1.f - t;
                        float s2 = fmaf(t * t, u, u);   // (1-t)(1+t^2)
                        den[id] += r * s2;
                    }
                }
    }

    // Reduce across the 4 lanes sharing a row (xor 1,2 stays within quad).
#pragma unroll
    for (int id = 0; id < 4; ++id) {
        num[id] += __shfl_xor_sync(0xffffffffu, num[id], 1);
        num[id] += __shfl_xor_sync(0xffffffffu, num[id], 2);
        den[id] += __shfl_xor_sync(0xffffffffu, den[id], 1);
        den[id] += __shfl_xor_sync(0xffffffffu, den[id], 2);
    }
    __syncthreads();
    if (cc == 0) {
#pragma unroll
        for (int mf = 0; mf < 2; ++mf)
#pragma unroll
            for (int hi = 0; hi < 2; ++hi) {
                int rl = wm * 32 + mf * 16 + g + hi * 8;
                red_n[rl][wn] = num[mf * 2 + hi];
                red_d[rl][wn] = den[mf * 2 + hi];
            }
    }
    __syncthreads();
    if (tid < BM) {
        g_num[h * N_PTS + row0 + tid] = red_n[tid][0] + red_n[tid][1];
        g_den[h * N_PTS + row0 + tid] = red_d[tid][0] + red_d[tid][1];
    }
}

// ---------------------------------------------------------------------------
// 1024 threads: loss = sum_r num_r*den_r / sum_c h^2 (N - h)
__global__ void finalize_kernel(float* __restrict__ out) {
    __shared__ double s1[1024];
    __shared__ double s2[1024];
    int t = threadIdx.x;
    double a = 0.0;
#pragma unroll
    for (int q = 0; q < N_PTS / 1024; ++q) {
        int row = t + q * 1024;
        double n = (double)g_num[row] + (double)g_num[N_PTS + row];
        double d = (double)g_den[row] + (double)g_den[N_PTS + row];
        a += n * d;
    }
    double b = 0.0;
    if (t < NUM_CLASSES) {
        double hh = (double)g_hist[t];
        b = hh * hh * ((double)N_PTS - hh);
    }
    s1[t] = a; s2[t] = b;
    __syncthreads();
    for (int o = 512; o; o >>= 1) {
        if (t < o) { s1[t] += s1[t + o]; s2[t] += s2[t + o]; }
        __syncthreads();
    }
    if (t == 0) out[0] = (float)(s1[0] / s2[0]);
}

// ---------------------------------------------------------------------------
extern "C" void kernel_launch(void* const* d_in, const int* in_sizes, int n_in,
                              void* d_out, int out_size) {
    const float* X   = (const float*)d_in[0];
    const int*   lab = (const int*)d_in[1];
    float*       out = (float*)d_out;

    zero_kernel<<<1, 128>>>();
    prep_kernel<<<N_PTS / 8, 256>>>(X, lab);

    size_t smem = (size_t)(BM + BN) * SAB * sizeof(__nv_bfloat16);  // 101,376 B
    cudaFuncSetAttribute(triplet_main_kernel,
                         cudaFuncAttributeMaxDynamicSharedMemorySize, (int)smem);
    triplet_main_kernel<<<NBLOCKS, 256, smem>>>(lab);

    finalize_kernel<<<1, 1024>>>(out);
}

// round 13
// speedup vs baseline: 5.4613x; 1.3758x over previous
#include <cuda_runtime.h>
#include <cuda_bf16.h>
#include <cstdint>

#define N_PTS 8192
#define E_DIM 256
#define NUM_CLASSES 100
#define MARGIN 0.1f
#define EPS_F 1e-4f

#define BM 128
#define BN 64
#define SAB 264             // padded row stride in bf16 elems (132 words == 4 mod 32)
#define NROWTILES (N_PTS / BM)    // 64
#define NBLOCKS (NROWTILES * 2)   // 128 (2 column halves)
#define HALF_TILES ((N_PTS / 2) / BN)  // 64 col tiles per half
#define NTHREADS 512

__device__ float g_sq[N_PTS];
__device__ int   g_hist[NUM_CLASSES];
__device__ float g_num[2 * N_PTS];
__device__ float g_den[2 * N_PTS];
__device__ unsigned g_done;
__device__ __nv_bfloat16 g_xb[(size_t)N_PTS * E_DIM];   // bf16 copy of X (4MB)

__device__ __forceinline__ void mma_bf16(float acc[4], const uint32_t a[4],
                                         const uint32_t b[2]) {
    asm volatile(
        "mma.sync.aligned.m16n8k16.row.col.f32.bf16.bf16.f32 "
        "{%0,%1,%2,%3}, {%4,%5,%6,%7}, {%8,%9}, {%0,%1,%2,%3};"
        : "+f"(acc[0]), "+f"(acc[1]), "+f"(acc[2]), "+f"(acc[3])
        : "r"(a[0]), "r"(a[1]), "r"(a[2]), "r"(a[3]), "r"(b[0]), "r"(b[1]));
}

// ---------------------------------------------------------------------------
__global__ void zero_kernel() {
    int t = threadIdx.x;
    if (t < NUM_CLASSES) g_hist[t] = 0;
    if (t == 0) g_done = 0u;
}

// Per-row squared norms + label histogram + bf16 conversion. One warp per row.
__global__ void prep_kernel(const float* __restrict__ X, const int* __restrict__ lab) {
    int warp = (blockIdx.x * blockDim.x + threadIdx.x) >> 5;
    int lane = threadIdx.x & 31;
    if (warp >= N_PTS) return;
    const float4* row = (const float4*)(X + (size_t)warp * E_DIM);
    float4 v0 = row[2 * lane];
    float4 v1 = row[2 * lane + 1];
    float s = v0.x * v0.x + v0.y * v0.y + v0.z * v0.z + v0.w * v0.w
            + v1.x * v1.x + v1.y * v1.y + v1.z * v1.z + v1.w * v1.w;

    __nv_bfloat162 p0 = __floats2bfloat162_rn(v0.x, v0.y);
    __nv_bfloat162 p1 = __floats2bfloat162_rn(v0.z, v0.w);
    __nv_bfloat162 p2 = __floats2bfloat162_rn(v1.x, v1.y);
    __nv_bfloat162 p3 = __floats2bfloat162_rn(v1.z, v1.w);
    uint4 u;
    u.x = *(uint32_t*)&p0; u.y = *(uint32_t*)&p1;
    u.z = *(uint32_t*)&p2; u.w = *(uint32_t*)&p3;
    ((uint4*)(g_xb + (size_t)warp * E_DIM))[lane] = u;

#pragma unroll
    for (int o = 16; o; o >>= 1) s += __shfl_xor_sync(0xffffffffu, s, o);
    if (lane == 0) {
        g_sq[warp] = s;
        atomicAdd(&g_hist[lab[warp]], 1);
    }
}

// ---------------------------------------------------------------------------
// bf16 m16n8k16 tensor-core Gram + fused triplet-ratio epilogue + fused final
// reduction (last CTA). 512 threads = 16 warps, warp grid 4(m) x 4(n),
// warp tile 32x16; 4 warps per SMSP for MMA/epilogue/load overlap.
// ---------------------------------------------------------------------------
__global__ void __launch_bounds__(NTHREADS, 1)
triplet_main_kernel(const int* __restrict__ lab, float* __restrict__ out) {
    extern __shared__ __nv_bfloat16 smb[];
    __nv_bfloat16* As = smb;                 // BM x SAB
    __nv_bfloat16* Bs = smb + BM * SAB;      // BN x SAB

    __shared__ float sqb_s[BN];
    __shared__ int   lbb_s[BN];
    __shared__ float red_n[BM][4];
    __shared__ float red_d[BM][4];
    __shared__ unsigned last_s;
    __shared__ double s1[NTHREADS];
    __shared__ double s2[NTHREADS];

    const int tid  = threadIdx.x;
    const int w    = tid >> 5, lane = tid & 31;
    const int wm   = w >> 2,   wn   = w & 3;       // 4x4 warp grid
    const int g    = lane >> 2, cc  = lane & 3;
    const int rt   = blockIdx.x >> 1;
    const int h    = blockIdx.x & 1;
    const int row0 = rt * BM;
    const int cbase = h * (N_PTS / 2);
    const float DIAG_D = sqrtf(EPS_F);

    // A tile (bf16, resident): 4096 uint4, 8 per thread.
#pragma unroll
    for (int q = 0; q < 8; ++q) {
        int idx = tid + q * NTHREADS;
        int r = idx >> 5, c8 = idx & 31;
        uint4 u = ((const uint4*)(g_xb + (size_t)(row0 + r) * E_DIM))[c8];
        *(uint4*)(As + (size_t)r * SAB + c8 * 8) = u;
    }

    float sqa[4]; int la[4];
#pragma unroll
    for (int mf = 0; mf < 2; ++mf)
#pragma unroll
        for (int hi = 0; hi < 2; ++hi) {
            int r = row0 + wm * 32 + mf * 16 + g + hi * 8;
            sqa[mf * 2 + hi] = g_sq[r];
            la[mf * 2 + hi]  = lab[r];
        }

    float num[4] = {0.f, 0.f, 0.f, 0.f};
    float den[4] = {0.f, 0.f, 0.f, 0.f};

    for (int jt = 0; jt < HALF_TILES; ++jt) {
        const int col0 = cbase + jt * BN;
        __syncthreads();  // previous tile's Bs fully consumed

        // B tile: 2048 uint4, 4 per thread (batched LDGs).
        {
            uint4 tmp[4];
#pragma unroll
            for (int q = 0; q < 4; ++q) {
                int idx = tid + q * NTHREADS;
                int r = idx >> 5, c8 = idx & 31;
                tmp[q] = ((const uint4*)(g_xb + (size_t)(col0 + r) * E_DIM))[c8];
            }
#pragma unroll
            for (int q = 0; q < 4; ++q) {
                int idx = tid + q * NTHREADS;
                int r = idx >> 5, c8 = idx & 31;
                *(uint4*)(Bs + (size_t)r * SAB + c8 * 8) = tmp[q];
            }
        }
        if (tid < BN) {
            sqb_s[tid] = g_sq[col0 + tid];
            lbb_s[tid] = lab[col0 + tid];
        }
        __syncthreads();

        float acc[2][2][4];
#pragma unroll
        for (int mf = 0; mf < 2; ++mf)
#pragma unroll
            for (int nf = 0; nf < 2; ++nf)
#pragma unroll
                for (int e = 0; e < 4; ++e) acc[mf][nf][e] = 0.f;

#pragma unroll 4
        for (int ks = 0; ks < E_DIM / 16; ++ks) {
            const int kc = ks * 16;
            uint32_t a[2][4], b[2][2];
#pragma unroll
            for (int mf = 0; mf < 2; ++mf) {
                int r = wm * 32 + mf * 16 + g;
                a[mf][0] = *(const uint32_t*)(As + (size_t)r * SAB + kc + 2 * cc);
                a[mf][1] = *(const uint32_t*)(As + (size_t)(r + 8) * SAB + kc + 2 * cc);
                a[mf][2] = *(const uint32_t*)(As + (size_t)r * SAB + kc + 2 * cc + 8);
                a[mf][3] = *(const uint32_t*)(As + (size_t)(r + 8) * SAB + kc + 2 * cc + 8);
            }
#pragma unroll
            for (int nf = 0; nf < 2; ++nf) {
                int n = wn * 16 + nf * 8 + g;
                b[nf][0] = *(const uint32_t*)(Bs + (size_t)n * SAB + kc + 2 * cc);
                b[nf][1] = *(const uint32_t*)(Bs + (size_t)n * SAB + kc + 2 * cc + 8);
            }
#pragma unroll
            for (int mf = 0; mf < 2; ++mf)
#pragma unroll
                for (int nf = 0; nf < 2; ++nf)
                    mma_bf16(acc[mf][nf], a[mf], b[nf]);
        }

        // Epilogue: one MUFU (rsqrt) per element; series for 1/(d+margin).
        float sj[2][2]; int lj[2][2];
#pragma unroll
        for (int nf = 0; nf < 2; ++nf)
#pragma unroll
            for (int e0 = 0; e0 < 2; ++e0) {
                int jl = wn * 16 + nf * 8 + 2 * cc + e0;
                sj[nf][e0] = sqb_s[jl];
                lj[nf][e0] = lbb_s[jl];
            }

#pragma unroll
        for (int mf = 0; mf < 2; ++mf)
#pragma unroll
            for (int nf = 0; nf < 2; ++nf)
#pragma unroll
                for (int e = 0; e < 4; ++e) {
                    int hi = e >> 1, e0 = e & 1;
                    int id = mf * 2 + hi;
                    int iglob = row0 + wm * 32 + mf * 16 + g + hi * 8;
                    int jglob = col0 + wn * 16 + nf * 8 + 2 * cc + e0;
                    float v = fmaxf(sqa[id] + sj[nf][e0] - 2.f * acc[mf][nf][e], EPS_F);
                    float r;
                    asm("rsqrt.approx.f32 %0, %1;" : "=f"(r) : "f"(v));
                    if (la[id] == lj[nf][e0]) {
                        num[id] += (iglob == jglob) ? DIAG_D : v * r;
                    } else {
                        float t  = MARGIN * r;
                        float u  = 1.f - t;
                        float s2v = fmaf(t * t, u, u);   // (1-t)(1+t^2)
                        den[id] += r * s2v;
                    }
                }
    }

    // Reduce across the 4 lanes sharing a row (xor 1,2 stays within quad).
#pragma unroll
    for (int id = 0; id < 4; ++id) {
        num[id] += __shfl_xor_sync(0xffffffffu, num[id], 1);
        num[id] += __shfl_xor_sync(0xffffffffu, num[id], 2);
        den[id] += __shfl_xor_sync(0xffffffffu, den[id], 1);
        den[id] += __shfl_xor_sync(0xffffffffu, den[id], 2);
    }
    __syncthreads();
    if (cc == 0) {
#pragma unroll
        for (int mf = 0; mf < 2; ++mf)
#pragma unroll
            for (int hi = 0; hi < 2; ++hi) {
                int rl = wm * 32 + mf * 16 + g + hi * 8;
                red_n[rl][wn] = num[mf * 2 + hi];
                red_d[rl][wn] = den[mf * 2 + hi];
            }
    }
    __syncthreads();
    if (tid < BM) {
        g_num[h * N_PTS + row0 + tid] = red_n[tid][0] + red_n[tid][1]
                                      + red_n[tid][2] + red_n[tid][3];
        g_den[h * N_PTS + row0 + tid] = red_d[tid][0] + red_d[tid][1]
                                      + red_d[tid][2] + red_d[tid][3];
    }

    // --- Fused finalize: last CTA to finish reduces everything. ---
    __syncthreads();
    if (tid == 0) {
        __threadfence();
        unsigned prev = atomicAdd(&g_done, 1u);
        last_s = (prev == NBLOCKS - 1) ? 1u : 0u;
    }
    __syncthreads();
    if (last_s) {
        __threadfence();
        double a = 0.0;
#pragma unroll
        for (int q = 0; q < N_PTS / NTHREADS; ++q) {
            int row = tid + q * NTHREADS;
            double n = (double)g_num[row] + (double)g_num[N_PTS + row];
            double d = (double)g_den[row] + (double)g_den[N_PTS + row];
            a += n * d;
        }
        double b = 0.0;
        if (tid < NUM_CLASSES) {
            double hh = (double)g_hist[tid];
            b = hh * hh * ((double)N_PTS - hh);
        }
        s1[tid] = a; s2[tid] = b;
        __syncthreads();
        for (int o = NTHREADS / 2; o; o >>= 1) {
            if (tid < o) { s1[tid] += s1[tid + o]; s2[tid] += s2[tid + o]; }
            __syncthreads();
        }
        if (tid == 0) out[0] = (float)(s1[0] / s2[0]);
    }
}

// ---------------------------------------------------------------------------
extern "C" void kernel_launch(void* const* d_in, const int* in_sizes, int n_in,
                              void* d_out, int out_size) {
    const float* X   = (const float*)d_in[0];
    const int*   lab = (const int*)d_in[1];
    float*       out = (float*)d_out;

    zero_kernel<<<1, 128>>>();
    prep_kernel<<<N_PTS / 8, 256>>>(X, lab);

    size_t smem = (size_t)(BM + BN) * SAB * sizeof(__nv_bfloat16);  // 101,376 B
    cudaFuncSetAttribute(triplet_main_kernel,
                         cudaFuncAttributeMaxDynamicSharedMemorySize, (int)smem);
    triplet_main_kernel<<<NBLOCKS, NTHREADS, smem>>>(lab, out);
}

// round 14
// speedup vs baseline: 9.5710x; 1.7525x over previous
#include <cuda_runtime.h>
#include <cuda_bf16.h>
#include <cstdint>

#define N_PTS 8192
#define E_DIM 256
#define NUM_CLASSES 100
#define MARGIN 0.1f
#define EPS_F 1e-4f

#define BT 128                        // tile edge (rows and cols)
#define SAB 264                       // padded row stride in bf16 elems
#define NRB (N_PTS / BT)              // 64 row blocks
#define NTILES (NRB * (NRB + 1) / 2)  // 2080 triangular tiles
#define NTHREADS 512

__device__ float g_sq[N_PTS];
__device__ int   g_hist[NUM_CLASSES];
__device__ float g_num[N_PTS];
__device__ float g_den[N_PTS];
__device__ unsigned g_done;
__device__ __nv_bfloat16 g_xb[(size_t)N_PTS * E_DIM];   // bf16 copy of X (4MB)

__device__ __forceinline__ void mma_bf16(float acc[4], const uint32_t a[4],
                                         const uint32_t b[2]) {
    asm volatile(
        "mma.sync.aligned.m16n8k16.row.col.f32.bf16.bf16.f32 "
        "{%0,%1,%2,%3}, {%4,%5,%6,%7}, {%8,%9}, {%0,%1,%2,%3};"
        : "+f"(acc[0]), "+f"(acc[1]), "+f"(acc[2]), "+f"(acc[3])
        : "r"(a[0]), "r"(a[1]), "r"(a[2]), "r"(a[3]), "r"(b[0]), "r"(b[1]));
}

// ---------------------------------------------------------------------------
__global__ void zero_kernel() {
    int t = threadIdx.x;
    for (int i = t; i < N_PTS; i += 1024) { g_num[i] = 0.f; g_den[i] = 0.f; }
    if (t < NUM_CLASSES) g_hist[t] = 0;
    if (t == 0) g_done = 0u;
}

// Per-row squared norms + label histogram + bf16 conversion. One warp per row.
__global__ void prep_kernel(const float* __restrict__ X, const int* __restrict__ lab) {
    int warp = (blockIdx.x * blockDim.x + threadIdx.x) >> 5;
    int lane = threadIdx.x & 31;
    if (warp >= N_PTS) return;
    const float4* row = (const float4*)(X + (size_t)warp * E_DIM);
    float4 v0 = row[2 * lane];
    float4 v1 = row[2 * lane + 1];
    float s = v0.x * v0.x + v0.y * v0.y + v0.z * v0.z + v0.w * v0.w
            + v1.x * v1.x + v1.y * v1.y + v1.z * v1.z + v1.w * v1.w;

    __nv_bfloat162 p0 = __floats2bfloat162_rn(v0.x, v0.y);
    __nv_bfloat162 p1 = __floats2bfloat162_rn(v0.z, v0.w);
    __nv_bfloat162 p2 = __floats2bfloat162_rn(v1.x, v1.y);
    __nv_bfloat162 p3 = __floats2bfloat162_rn(v1.z, v1.w);
    uint4 u;
    u.x = *(uint32_t*)&p0; u.y = *(uint32_t*)&p1;
    u.z = *(uint32_t*)&p2; u.w = *(uint32_t*)&p3;
    ((uint4*)(g_xb + (size_t)warp * E_DIM))[lane] = u;

#pragma unroll
    for (int o = 16; o; o >>= 1) s += __shfl_xor_sync(0xffffffffu, s, o);
    if (lane == 0) {
        g_sq[warp] = s;
        atomicAdd(&g_hist[lab[warp]], 1);
    }
}

// ---------------------------------------------------------------------------
// Symmetric-Gram bf16 m16n8k16 kernel. One CTA per triangular tile (I,J), J<=I.
// Off-diagonal tiles scatter BOTH row-side (I) and column-side (J) partials.
// 512 threads = 16 warps, warp grid 4(m) x 4(n), warp tile 32x32.
// Last CTA performs the final reduction.
// ---------------------------------------------------------------------------
__global__ void __launch_bounds__(NTHREADS, 1)
triplet_main_kernel(const int* __restrict__ lab, float* __restrict__ out) {
    extern __shared__ __nv_bfloat16 smb[];
    __nv_bfloat16* As = smb;                 // BT x SAB (rows of I)
    __nv_bfloat16* Bs = smb + BT * SAB;      // BT x SAB (rows of J = columns)

    __shared__ float sqb_s[BT];
    __shared__ int   lbb_s[BT];
    __shared__ float red_n[BT][4];
    __shared__ float red_d[BT][4];
    __shared__ float colp_n[4][BT];
    __shared__ float colp_d[4][BT];
    __shared__ unsigned last_s;
    __shared__ double s1[NTHREADS];
    __shared__ double s2[NTHREADS];

    const int tid  = threadIdx.x;
    const int w    = tid >> 5, lane = tid & 31;
    const int wm   = w >> 2,   wn   = w & 3;       // 4x4 warp grid
    const int g    = lane >> 2, cc  = lane & 3;

    // Triangular decode: blockIdx.x -> (I, J), J <= I.
    int b = blockIdx.x;
    int I = (int)((sqrtf(8.f * (float)b + 1.f) - 1.f) * 0.5f);
    while ((I + 1) * (I + 2) / 2 <= b) ++I;
    while (I * (I + 1) / 2 > b) --I;
    const int J = b - I * (I + 1) / 2;
    const bool offdiag = (I != J);

    const int row0 = I * BT;
    const int col0 = J * BT;
    const float DIAG_D = sqrtf(EPS_F);

    // Load A (I rows) and B (J rows): 4096 uint4 each, 8 per thread each.
#pragma unroll
    for (int q = 0; q < 8; ++q) {
        int idx = tid + q * NTHREADS;
        int r = idx >> 5, c8 = idx & 31;
        uint4 u = ((const uint4*)(g_xb + (size_t)(row0 + r) * E_DIM))[c8];
        *(uint4*)(As + (size_t)r * SAB + c8 * 8) = u;
    }
#pragma unroll
    for (int q = 0; q < 8; ++q) {
        int idx = tid + q * NTHREADS;
        int r = idx >> 5, c8 = idx & 31;
        uint4 u = ((const uint4*)(g_xb + (size_t)(col0 + r) * E_DIM))[c8];
        *(uint4*)(Bs + (size_t)r * SAB + c8 * 8) = u;
    }
    if (tid < BT) {
        sqb_s[tid] = g_sq[col0 + tid];
        lbb_s[tid] = lab[col0 + tid];
    }

    float sqa[4]; int la[4];
#pragma unroll
    for (int mf = 0; mf < 2; ++mf)
#pragma unroll
        for (int hi = 0; hi < 2; ++hi) {
            int r = row0 + wm * 32 + mf * 16 + g + hi * 8;
            sqa[mf * 2 + hi] = g_sq[r];
            la[mf * 2 + hi]  = lab[r];
        }
    __syncthreads();

    float acc[2][4][4];
#pragma unroll
    for (int mf = 0; mf < 2; ++mf)
#pragma unroll
        for (int nf = 0; nf < 4; ++nf)
#pragma unroll
            for (int e = 0; e < 4; ++e) acc[mf][nf][e] = 0.f;

#pragma unroll 4
    for (int ks = 0; ks < E_DIM / 16; ++ks) {
        const int kc = ks * 16;
        uint32_t a[2][4], bb[4][2];
#pragma unroll
        for (int mf = 0; mf < 2; ++mf) {
            int r = wm * 32 + mf * 16 + g;
            a[mf][0] = *(const uint32_t*)(As + (size_t)r * SAB + kc + 2 * cc);
            a[mf][1] = *(const uint32_t*)(As + (size_t)(r + 8) * SAB + kc + 2 * cc);
            a[mf][2] = *(const uint32_t*)(As + (size_t)r * SAB + kc + 2 * cc + 8);
            a[mf][3] = *(const uint32_t*)(As + (size_t)(r + 8) * SAB + kc + 2 * cc + 8);
        }
#pragma unroll
        for (int nf = 0; nf < 4; ++nf) {
            int n = wn * 32 + nf * 8 + g;
            bb[nf][0] = *(const uint32_t*)(Bs + (size_t)n * SAB + kc + 2 * cc);
            bb[nf][1] = *(const uint32_t*)(Bs + (size_t)n * SAB + kc + 2 * cc + 8);
        }
#pragma unroll
        for (int mf = 0; mf < 2; ++mf)
#pragma unroll
            for (int nf = 0; nf < 4; ++nf)
                mma_bf16(acc[mf][nf], a[mf], bb[nf]);
    }

    // Epilogue: one rsqrt per element; value feeds row (I) and column (J) sums.
    float num[4] = {0.f, 0.f, 0.f, 0.f};
    float den[4] = {0.f, 0.f, 0.f, 0.f};
    float cn[8]  = {0.f, 0.f, 0.f, 0.f, 0.f, 0.f, 0.f, 0.f};
    float cd[8]  = {0.f, 0.f, 0.f, 0.f, 0.f, 0.f, 0.f, 0.f};

    float sj[4][2]; int lj[4][2];
#pragma unroll
    for (int nf = 0; nf < 4; ++nf)
#pragma unroll
        for (int e0 = 0; e0 < 2; ++e0) {
            int jl = wn * 32 + nf * 8 + 2 * cc + e0;
            sj[nf][e0] = sqb_s[jl];
            lj[nf][e0] = lbb_s[jl];
        }

#pragma unroll
    for (int mf = 0; mf < 2; ++mf)
#pragma unroll
        for (int nf = 0; nf < 4; ++nf)
#pragma unroll
            for (int e = 0; e < 4; ++e) {
                int hi = e >> 1, e0 = e & 1;
                int id = mf * 2 + hi;
                int ci = nf * 2 + e0;
                float v = fmaxf(sqa[id] + sj[nf][e0] - 2.f * acc[mf][nf][e], EPS_F);
                float r;
                asm("rsqrt.approx.f32 %0, %1;" : "=f"(r) : "f"(v));
                if (la[id] == lj[nf][e0]) {
                    float c;
                    if (offdiag) {
                        c = v * r;
                    } else {
                        int il = wm * 32 + mf * 16 + g + hi * 8;
                        int jl = wn * 32 + nf * 8 + 2 * cc + e0;
                        c = (il == jl) ? DIAG_D : v * r;
                    }
                    num[id] += c;
                    cn[ci]  += c;
                } else {
                    float t = MARGIN * r;
                    float u = 1.f - t;
                    float c = r * fmaf(t * t, u, u);   // 1/(d+m) ~ r(1-t)(1+t^2)
                    den[id] += c;
                    cd[ci]  += c;
                }
            }

    // ---- Row-side reduce (over cc: xor 1,2 stays within quad) ----
#pragma unroll
    for (int id = 0; id < 4; ++id) {
        num[id] += __shfl_xor_sync(0xffffffffu, num[id], 1);
        num[id] += __shfl_xor_sync(0xffffffffu, num[id], 2);
        den[id] += __shfl_xor_sync(0xffffffffu, den[id], 1);
        den[id] += __shfl_xor_sync(0xffffffffu, den[id], 2);
    }
    if (cc == 0) {
#pragma unroll
        for (int mf = 0; mf < 2; ++mf)
#pragma unroll
            for (int hi = 0; hi < 2; ++hi) {
                int rl = wm * 32 + mf * 16 + g + hi * 8;
                red_n[rl][wn] = num[mf * 2 + hi];
                red_d[rl][wn] = den[mf * 2 + hi];
            }
    }

    // ---- Column-side reduce (over g: xor 4,8,16) ----
    if (offdiag) {
#pragma unroll
        for (int ci = 0; ci < 8; ++ci) {
            cn[ci] += __shfl_xor_sync(0xffffffffu, cn[ci], 4);
            cn[ci] += __shfl_xor_sync(0xffffffffu, cn[ci], 8);
            cn[ci] += __shfl_xor_sync(0xffffffffu, cn[ci], 16);
            cd[ci] += __shfl_xor_sync(0xffffffffu, cd[ci], 4);
            cd[ci] += __shfl_xor_sync(0xffffffffu, cd[ci], 8);
            cd[ci] += __shfl_xor_sync(0xffffffffu, cd[ci], 16);
        }
        if (g == 0) {
#pragma unroll
            for (int ci = 0; ci < 8; ++ci) {
                int nf = ci >> 1, e0 = ci & 1;
                int jl = wn * 32 + nf * 8 + 2 * cc + e0;
                colp_n[wm][jl] = cn[ci];
                colp_d[wm][jl] = cd[ci];
            }
        }
    }
    __syncthreads();

    if (tid < BT) {
        atomicAdd(&g_num[row0 + tid], red_n[tid][0] + red_n[tid][1]
                                    + red_n[tid][2] + red_n[tid][3]);
        atomicAdd(&g_den[row0 + tid], red_d[tid][0] + red_d[tid][1]
                                    + red_d[tid][2] + red_d[tid][3]);
        if (offdiag) {
            atomicAdd(&g_num[col0 + tid], colp_n[0][tid] + colp_n[1][tid]
                                        + colp_n[2][tid] + colp_n[3][tid]);
            atomicAdd(&g_den[col0 + tid], colp_d[0][tid] + colp_d[1][tid]
                                        + colp_d[2][tid] + colp_d[3][tid]);
        }
    }

    // --- Fused finalize: last CTA reduces everything. ---
    __syncthreads();
    if (tid == 0) {
        __threadfence();
        unsigned prev = atomicAdd(&g_done, 1u);
        last_s = (prev == NTILES - 1) ? 1u : 0u;
    }
    __syncthreads();
    if (last_s) {
        __threadfence();
        double a = 0.0;
#pragma unroll
        for (int q = 0; q < N_PTS / NTHREADS; ++q) {
            int row = tid + q * NTHREADS;
            a += (double)g_num[row] * (double)g_den[row];
        }
        double bb = 0.0;
        if (tid < NUM_CLASSES) {
            double hh = (double)g_hist[tid];
            bb = hh * hh * ((double)N_PTS - hh);
        }
        s1[tid] = a; s2[tid] = bb;
        __syncthreads();
        for (int o = NTHREADS / 2; o; o >>= 1) {
            if (tid < o) { s1[tid] += s1[tid + o]; s2[tid] += s2[tid + o]; }
            __syncthreads();
        }
        if (tid == 0) out[0] = (float)(s1[0] / s2[0]);
    }
}

// ---------------------------------------------------------------------------
extern "C" void kernel_launch(void* const* d_in, const int* in_sizes, int n_in,
                              void* d_out, int out_size) {
    const float* X   = (const float*)d_in[0];
    const int*   lab = (const int*)d_in[1];
    float*       out = (float*)d_out;

    zero_kernel<<<1, 1024>>>();
    prep_kernel<<<N_PTS / 8, 256>>>(X, lab);

    size_t smem = (size_t)2 * BT * SAB * sizeof(__nv_bfloat16);  // 135,168 B
    cudaFuncSetAttribute(triplet_main_kernel,
                         cudaFuncAttributeMaxDynamicSharedMemorySize, (int)smem);
    triplet_main_kernel<<<NTILES, NTHREADS, smem>>>(lab, out);
}